// round 1
// baseline (speedup 1.0000x reference)
#include <cuda_runtime.h>

#define NB 32
#define IJ 1024
#define ND 128
#define NK 64
#define CHUNKS 16
#define ROWS 64          // ij rows per stage1 CTA (IJ / CHUNKS)
#define CT_STR 65        // padded stride for transposed centers in smem

// ---------------- scratch (device globals; no allocation) ----------------
__device__ float g_psum[NB * CHUNKS * NK * ND];   // 16 MB partial vlad sums
__device__ float g_ssum[NB * CHUNKS * NK];        // partial sum of sim over rows
__device__ float g_sqpart[NB * NK];               // per-(b,k) squared-sum partials
__device__ float g_scale;                         // 1/global_norm

// ---------------- stage 1: fc GEMM + softmax + sim^T @ f partial ----------
__global__ __launch_bounds__(256, 2)
void nv_stage1(const float* __restrict__ feat, const float* __restrict__ cent) {
    extern __shared__ float sm[];
    float* cT  = sm;                       // [ND][CT_STR] transposed centers
    float* fsm = cT + ND * CT_STR;         // [ROWS][ND]
    float* sim = fsm + ROWS * ND;          // [ROWS][NK]
    float* f2  = sim + ROWS * NK;          // [ROWS]
    float* c2  = f2 + ROWS;                // [NK]

    const int b     = blockIdx.y;
    const int chunk = blockIdx.x;
    const int tid   = threadIdx.x;

    const float* cb = cent + (size_t)b * NK * ND;
    const float* fb = feat + (size_t)b * IJ * ND + (size_t)chunk * ROWS * ND;

    // load centers transposed (padded stride -> conflict-free everywhere)
    for (int i = tid; i < NK * ND; i += 256) {
        int k = i >> 7, d = i & 127;
        cT[d * CT_STR + k] = cb[i];
    }
    // load feature tile
    for (int i = tid; i < ROWS * ND; i += 256)
        fsm[i] = fb[i];
    __syncthreads();

    const int w    = tid >> 5;
    const int lane = tid & 31;

    // c2[k] = ||c_k||^2   (threads 0..63, column reads are conflict-free)
    if (tid < NK) {
        float s = 0.f;
        #pragma unroll 8
        for (int d = 0; d < ND; d++) {
            float v = cT[d * CT_STR + tid];
            s += v * v;
        }
        c2[tid] = s;
    }
    // f2[r] = ||f_r||^2 : warp w handles rows [8w, 8w+8)
    for (int r = w * 8; r < w * 8 + 8; r++) {
        float s = 0.f;
        #pragma unroll
        for (int d = lane; d < ND; d += 32) {
            float v = fsm[r * ND + d];
            s += v * v;
        }
        #pragma unroll
        for (int o = 16; o; o >>= 1) s += __shfl_xor_sync(0xffffffffu, s, o);
        s = __shfl_sync(0xffffffffu, s, 0);
        if (lane == 0) f2[r] = s;
    }
    __syncthreads();

    // fc dot products + softmax per row.  lane owns k=lane and k=lane+32.
    for (int r = w * 8; r < w * 8 + 8; r++) {
        float a0 = 0.f, a1 = 0.f;
        const float* frow = fsm + r * ND;
        #pragma unroll 8
        for (int d = 0; d < ND; d++) {
            float fv = frow[d];                       // broadcast
            a0 += fv * cT[d * CT_STR + lane];         // conflict-free
            a1 += fv * cT[d * CT_STR + lane + 32];
        }
        // m = -alpha*d2 = 2*fc - f2 - c2   (alpha = 1)
        float m0 = 2.f * a0 - f2[r] - c2[lane];
        float m1 = 2.f * a1 - f2[r] - c2[lane + 32];
        float mx = fmaxf(m0, m1);
        #pragma unroll
        for (int o = 16; o; o >>= 1) mx = fmaxf(mx, __shfl_xor_sync(0xffffffffu, mx, o));
        float e0 = __expf(m0 - mx);
        float e1 = __expf(m1 - mx);
        float s  = e0 + e1;
        #pragma unroll
        for (int o = 16; o; o >>= 1) s += __shfl_xor_sync(0xffffffffu, s, o);
        float inv = 1.f / s;
        sim[r * NK + lane]      = e0 * inv;
        sim[r * NK + lane + 32] = e1 * inv;
    }
    __syncthreads();

    // partial vlad:  psum[k][d] = sum_r sim[r][k] * f[r][d]
    // 256 threads as 16(ty: k-tiles of 4) x 16(tx: d-tiles of 8)
    const int ty = tid >> 4;
    const int tx = tid & 15;
    const int k0 = ty * 4;
    const int d0 = tx * 8;

    float acc[4][8];
    #pragma unroll
    for (int i = 0; i < 4; i++)
        #pragma unroll
        for (int j = 0; j < 8; j++) acc[i][j] = 0.f;
    float ssl[4] = {0.f, 0.f, 0.f, 0.f};

    for (int r = 0; r < ROWS; r++) {
        float s0 = sim[r * NK + k0 + 0];
        float s1 = sim[r * NK + k0 + 1];
        float s2 = sim[r * NK + k0 + 2];
        float s3 = sim[r * NK + k0 + 3];
        float4 fa = *reinterpret_cast<const float4*>(&fsm[r * ND + d0]);
        float4 fbv = *reinterpret_cast<const float4*>(&fsm[r * ND + d0 + 4]);
        float fv[8] = {fa.x, fa.y, fa.z, fa.w, fbv.x, fbv.y, fbv.z, fbv.w};
        #pragma unroll
        for (int j = 0; j < 8; j++) {
            acc[0][j] += s0 * fv[j];
            acc[1][j] += s1 * fv[j];
            acc[2][j] += s2 * fv[j];
            acc[3][j] += s3 * fv[j];
        }
        ssl[0] += s0; ssl[1] += s1; ssl[2] += s2; ssl[3] += s3;
    }

    float* op = g_psum + (((size_t)(b * CHUNKS + chunk) * NK + k0) * ND) + d0;
    #pragma unroll
    for (int i = 0; i < 4; i++) {
        *reinterpret_cast<float4*>(op + i * ND) =
            make_float4(acc[i][0], acc[i][1], acc[i][2], acc[i][3]);
        *reinterpret_cast<float4*>(op + i * ND + 4) =
            make_float4(acc[i][4], acc[i][5], acc[i][6], acc[i][7]);
    }
    if (tx == 0) {
        #pragma unroll
        for (int i = 0; i < 4; i++)
            g_ssum[(b * CHUNKS + chunk) * NK + k0 + i] = ssl[i];
    }
}

// ---------------- stage 2: reduce chunks, subtract ssum*c, partial sq-sum --
__global__ void nv_stage2(const float* __restrict__ cent, float* __restrict__ out) {
    const int bk = blockIdx.x;            // 0 .. NB*NK-1
    const int b  = bk >> 6;
    const int k  = bk & 63;
    const int d  = threadIdx.x;           // 128 threads

    float v = 0.f;
    #pragma unroll
    for (int ch = 0; ch < CHUNKS; ch++)
        v += g_psum[((size_t)(b * CHUNKS + ch) * NK + k) * ND + d];

    float ss = 0.f;
    #pragma unroll
    for (int ch = 0; ch < CHUNKS; ch++)
        ss += g_ssum[(b * CHUNKS + ch) * NK + k];

    float o = v - ss * cent[((size_t)b * NK + k) * ND + d];
    out[((size_t)b * NK + k) * ND + d] = o;

    // block-reduce o*o
    float sq = o * o;
    #pragma unroll
    for (int off = 16; off; off >>= 1) sq += __shfl_xor_sync(0xffffffffu, sq, off);
    __shared__ float red[4];
    if ((d & 31) == 0) red[d >> 5] = sq;
    __syncthreads();
    if (d == 0)
        g_sqpart[bk] = red[0] + red[1] + red[2] + red[3];
}

// ---------------- stage 3: global norm -> scale ---------------------------
__global__ void nv_stage3() {
    const int tid = threadIdx.x;          // 256 threads
    float s = 0.f;
    for (int i = tid; i < NB * NK; i += 256) s += g_sqpart[i];
    #pragma unroll
    for (int off = 16; off; off >>= 1) s += __shfl_xor_sync(0xffffffffu, s, off);
    __shared__ float red[8];
    if ((tid & 31) == 0) red[tid >> 5] = s;
    __syncthreads();
    if (tid == 0) {
        float t = 0.f;
        #pragma unroll
        for (int i = 0; i < 8; i++) t += red[i];
        g_scale = rsqrtf(fmaxf(t, 1e-12f));
    }
}

// ---------------- stage 4: apply scale ------------------------------------
__global__ void nv_stage4(float* __restrict__ out) {
    const int i = blockIdx.x * blockDim.x + threadIdx.x;   // 65536 float4s
    float sc = g_scale;
    float4* o4 = reinterpret_cast<float4*>(out);
    float4 v = o4[i];
    v.x *= sc; v.y *= sc; v.z *= sc; v.w *= sc;
    o4[i] = v;
}

// ---------------- launch ---------------------------------------------------
extern "C" void kernel_launch(void* const* d_in, const int* in_sizes, int n_in,
                              void* d_out, int out_size) {
    const float* feat = (const float*)d_in[0];   // (32,32,32,128) fp32
    const float* cent = (const float*)d_in[1];   // (32,64,128)    fp32
    float* out = (float*)d_out;                  // (32, 8192)     fp32

    const int smem1 = (ND * CT_STR + ROWS * ND + ROWS * NK + ROWS + NK) * (int)sizeof(float);
    cudaFuncSetAttribute(nv_stage1, cudaFuncAttributeMaxDynamicSharedMemorySize, smem1);

    nv_stage1<<<dim3(CHUNKS, NB), 256, smem1>>>(feat, cent);
    nv_stage2<<<NB * NK, 128>>>(cent, out);
    nv_stage3<<<1, 256>>>();
    nv_stage4<<<(NB * NK * ND / 4) / 256, 256>>>(out);
}

// round 2
// speedup vs baseline: 1.5180x; 1.5180x over previous
#include <cuda_runtime.h>

#define NB 32
#define IJ 1024
#define ND 128
#define NK 64
#define CHUNKS 16
#define ROWS 64          // ij rows per stage1 CTA
#define FSTR 132         // padded smem row stride (floats) for f tile
#define CSTR 132         // padded smem row stride (floats) for c tile

typedef unsigned long long ull;

// ---------------- f32x2 packed helpers ------------------------------------
__device__ __forceinline__ ull ffma2(ull a, ull b, ull c) {
    ull d;
    asm("fma.rn.f32x2 %0, %1, %2, %3;" : "=l"(d) : "l"(a), "l"(b), "l"(c));
    return d;
}
__device__ __forceinline__ ull pack2(float lo, float hi) {
    ull r;
    asm("mov.b64 %0, {%1, %2};" : "=l"(r) : "f"(lo), "f"(hi));
    return r;
}
__device__ __forceinline__ float2 unpack2(ull v) {
    float2 f;
    asm("mov.b64 {%0, %1}, %2;" : "=f"(f.x), "=f"(f.y) : "l"(v));
    return f;
}

// ---------------- scratch (device globals; no allocation) ----------------
__device__ float g_psum[NB * CHUNKS * NK * ND];   // 16 MB partial vlad sums
__device__ float g_ssum[NB * CHUNKS * NK];        // partial sum of sim over rows
__device__ float g_sqpart[NB * NK];               // per-(b,k) squared-sum partials
__device__ float g_scale;                         // 1/global_norm

// ---------------- stage 1: fc GEMM + softmax + sim^T @ f partial ----------
__global__ __launch_bounds__(256, 2)
void nv_stage1(const float* __restrict__ feat, const float* __restrict__ cent) {
    extern __shared__ float sm[];
    float* fsm = sm;                         // [ROWS][FSTR]
    float* csm = fsm + ROWS * FSTR;          // [NK][CSTR]
    float* sim = csm + NK * CSTR;            // [ROWS][NK]
    float* f2  = sim + ROWS * NK;            // [ROWS]
    float* c2  = f2 + ROWS;                  // [NK]

    const int b     = blockIdx.y;
    const int chunk = blockIdx.x;
    const int tid   = threadIdx.x;

    const float* cb = cent + (size_t)b * NK * ND;
    const float* fb = feat + (size_t)b * IJ * ND + (size_t)chunk * ROWS * ND;

    // ---- load tiles (coalesced float4, conflict-free stores) ----
    #pragma unroll
    for (int p = 0; p < 8; p++) {                  // 64*32 float4 / 256 thr
        int i = tid + p * 256;
        int r = i >> 5, c4 = (i & 31) << 2;
        *reinterpret_cast<float4*>(&fsm[r * FSTR + c4]) =
            *reinterpret_cast<const float4*>(&fb[r * ND + c4]);
        *reinterpret_cast<float4*>(&csm[r * CSTR + c4]) =
            *reinterpret_cast<const float4*>(&cb[r * ND + c4]);
    }
    __syncthreads();

    const int w    = tid >> 5;
    const int lane = tid & 31;

    // ---- f2[r] = ||f_r||^2 and c2[k] = ||c_k||^2 (warp per 8 rows) ----
    #pragma unroll
    for (int rr = 0; rr < 8; rr++) {
        int r = w * 8 + rr;
        float sf = 0.f, sc = 0.f;
        #pragma unroll
        for (int d = lane; d < ND; d += 32) {
            float vf = fsm[r * FSTR + d];
            float vc = csm[r * CSTR + d];
            sf += vf * vf;
            sc += vc * vc;
        }
        #pragma unroll
        for (int o = 16; o; o >>= 1) {
            sf += __shfl_xor_sync(0xffffffffu, sf, o);
            sc += __shfl_xor_sync(0xffffffffu, sc, o);
        }
        if (lane == 0) { f2[r] = sf; c2[r] = sc; }
    }
    __syncthreads();

    // ---- phase A: fc[r][k] via f32x2 dot products ----
    {
        const int tx = tid & 15;     // k = tx + 16j
        const int ty = tid >> 4;     // rows 4ty..4ty+3
        ull acc[4][4];
        #pragma unroll
        for (int i = 0; i < 4; i++)
            #pragma unroll
            for (int j = 0; j < 4; j++) acc[i][j] = 0ull;

        #pragma unroll 4
        for (int d = 0; d < ND; d += 4) {
            ulonglong2 af[4], cf[4];
            #pragma unroll
            for (int i = 0; i < 4; i++)
                af[i] = *reinterpret_cast<const ulonglong2*>(&fsm[(4 * ty + i) * FSTR + d]);
            #pragma unroll
            for (int j = 0; j < 4; j++)
                cf[j] = *reinterpret_cast<const ulonglong2*>(&csm[(tx + 16 * j) * CSTR + d]);
            #pragma unroll
            for (int i = 0; i < 4; i++)
                #pragma unroll
                for (int j = 0; j < 4; j++) {
                    acc[i][j] = ffma2(af[i].x, cf[j].x, acc[i][j]);
                    acc[i][j] = ffma2(af[i].y, cf[j].y, acc[i][j]);
                }
        }
        #pragma unroll
        for (int i = 0; i < 4; i++)
            #pragma unroll
            for (int j = 0; j < 4; j++) {
                float2 u = unpack2(acc[i][j]);
                sim[(4 * ty + i) * NK + tx + 16 * j] = u.x + u.y;
            }
    }
    __syncthreads();

    // ---- softmax per row (warp per 8 rows; lane owns k=lane, k=lane+32) ----
    #pragma unroll
    for (int rr = 0; rr < 8; rr++) {
        int r = w * 8 + rr;
        float a0 = sim[r * NK + lane];
        float a1 = sim[r * NK + lane + 32];
        float m0 = 2.f * a0 - f2[r] - c2[lane];
        float m1 = 2.f * a1 - f2[r] - c2[lane + 32];
        float mx = fmaxf(m0, m1);
        #pragma unroll
        for (int o = 16; o; o >>= 1) mx = fmaxf(mx, __shfl_xor_sync(0xffffffffu, mx, o));
        float e0 = __expf(m0 - mx);
        float e1 = __expf(m1 - mx);
        float s  = e0 + e1;
        #pragma unroll
        for (int o = 16; o; o >>= 1) s += __shfl_xor_sync(0xffffffffu, s, o);
        float inv = 1.f / s;
        sim[r * NK + lane]      = e0 * inv;
        sim[r * NK + lane + 32] = e1 * inv;
    }
    __syncthreads();

    // ---- phase B: psum[k][d] = sum_r sim[r][k] * f[r][d]  (f32x2) ----
    {
        const int tx = tid & 15;     // d0 = 8*tx
        const int ty = tid >> 4;     // k0 = 4*ty
        const int d0 = tx << 3;
        const int k0 = ty << 2;

        ull acc[4][4];
        #pragma unroll
        for (int i = 0; i < 4; i++)
            #pragma unroll
            for (int m = 0; m < 4; m++) acc[i][m] = 0ull;
        float ssl[4] = {0.f, 0.f, 0.f, 0.f};

        #pragma unroll 2
        for (int r = 0; r < ROWS; r++) {
            float4 s = *reinterpret_cast<const float4*>(&sim[r * NK + k0]);
            ulonglong2 fa = *reinterpret_cast<const ulonglong2*>(&fsm[r * FSTR + d0]);
            ulonglong2 fbv = *reinterpret_cast<const ulonglong2*>(&fsm[r * FSTR + d0 + 4]);
            ull sd[4];
            sd[0] = pack2(s.x, s.x);
            sd[1] = pack2(s.y, s.y);
            sd[2] = pack2(s.z, s.z);
            sd[3] = pack2(s.w, s.w);
            #pragma unroll
            for (int i = 0; i < 4; i++) {
                acc[i][0] = ffma2(sd[i], fa.x,  acc[i][0]);
                acc[i][1] = ffma2(sd[i], fa.y,  acc[i][1]);
                acc[i][2] = ffma2(sd[i], fbv.x, acc[i][2]);
                acc[i][3] = ffma2(sd[i], fbv.y, acc[i][3]);
            }
            ssl[0] += s.x; ssl[1] += s.y; ssl[2] += s.z; ssl[3] += s.w;
        }

        float* op = g_psum + (((size_t)(b * CHUNKS + chunk) * NK + k0) * ND) + d0;
        #pragma unroll
        for (int i = 0; i < 4; i++) {
            ulonglong2 v0; v0.x = acc[i][0]; v0.y = acc[i][1];
            ulonglong2 v1; v1.x = acc[i][2]; v1.y = acc[i][3];
            *reinterpret_cast<ulonglong2*>(op + i * ND)     = v0;
            *reinterpret_cast<ulonglong2*>(op + i * ND + 4) = v1;
        }
        if (tx == 0) {
            #pragma unroll
            for (int i = 0; i < 4; i++)
                g_ssum[(b * CHUNKS + chunk) * NK + k0 + i] = ssl[i];
        }
    }
}

// ---------------- stage 2: reduce chunks, subtract ssum*c, partial sq-sum --
__global__ void nv_stage2(const float* __restrict__ cent, float* __restrict__ out) {
    const int bk = blockIdx.x;            // 0 .. NB*NK-1
    const int b  = bk >> 6;
    const int k  = bk & 63;
    const int d  = threadIdx.x;           // 128 threads

    float v = 0.f;
    #pragma unroll
    for (int ch = 0; ch < CHUNKS; ch++)
        v += g_psum[((size_t)(b * CHUNKS + ch) * NK + k) * ND + d];

    float ss = 0.f;
    #pragma unroll
    for (int ch = 0; ch < CHUNKS; ch++)
        ss += g_ssum[(b * CHUNKS + ch) * NK + k];

    float o = v - ss * cent[((size_t)b * NK + k) * ND + d];
    out[((size_t)b * NK + k) * ND + d] = o;

    float sq = o * o;
    #pragma unroll
    for (int off = 16; off; off >>= 1) sq += __shfl_xor_sync(0xffffffffu, sq, off);
    __shared__ float red[4];
    if ((d & 31) == 0) red[d >> 5] = sq;
    __syncthreads();
    if (d == 0)
        g_sqpart[bk] = red[0] + red[1] + red[2] + red[3];
}

// ---------------- stage 3: global norm -> scale ---------------------------
__global__ void nv_stage3() {
    const int tid = threadIdx.x;          // 256 threads
    float s = 0.f;
    for (int i = tid; i < NB * NK; i += 256) s += g_sqpart[i];
    #pragma unroll
    for (int off = 16; off; off >>= 1) s += __shfl_xor_sync(0xffffffffu, s, off);
    __shared__ float red[8];
    if ((tid & 31) == 0) red[tid >> 5] = s;
    __syncthreads();
    if (tid == 0) {
        float t = 0.f;
        #pragma unroll
        for (int i = 0; i < 8; i++) t += red[i];
        g_scale = rsqrtf(fmaxf(t, 1e-12f));
    }
}

// ---------------- stage 4: apply scale (2 float4 / thread, MLP=2) ---------
__global__ void nv_stage4(float* __restrict__ out) {
    const int i = blockIdx.x * blockDim.x + threadIdx.x;   // 32768 threads
    const float sc = g_scale;
    float4* o4 = reinterpret_cast<float4*>(out);
    float4 v0 = o4[i];
    float4 v1 = o4[i + 32768];
    v0.x *= sc; v0.y *= sc; v0.z *= sc; v0.w *= sc;
    v1.x *= sc; v1.y *= sc; v1.z *= sc; v1.w *= sc;
    o4[i] = v0;
    o4[i + 32768] = v1;
}

// ---------------- launch ---------------------------------------------------
extern "C" void kernel_launch(void* const* d_in, const int* in_sizes, int n_in,
                              void* d_out, int out_size) {
    const float* feat = (const float*)d_in[0];   // (32,32,32,128) fp32
    const float* cent = (const float*)d_in[1];   // (32,64,128)    fp32
    float* out = (float*)d_out;                  // (32, 8192)     fp32

    const int smem1 = (ROWS * FSTR + NK * CSTR + ROWS * NK + ROWS + NK) * (int)sizeof(float);
    cudaFuncSetAttribute(nv_stage1, cudaFuncAttributeMaxDynamicSharedMemorySize, smem1);

    nv_stage1<<<dim3(CHUNKS, NB), 256, smem1>>>(feat, cent);
    nv_stage2<<<NB * NK, 128>>>(cent, out);
    nv_stage3<<<1, 256>>>();
    nv_stage4<<<128, 256>>>(out);
}

// round 5
// speedup vs baseline: 3.7649x; 2.4802x over previous
#include <cuda_runtime.h>
#include <cuda_bf16.h>
#include <cstdint>

#define NB 32
#define IJ 1024
#define ND 128
#define NK 64
#define CHUNKS 8
#define ROWS 128

#define FSTRB 272      // byte stride, f/c bf16 tiles (136 bf16, conflict-free for ldmatrix)
#define SSTRB 144      // byte stride, sim bf16 tiles (72 bf16)

// smem layout (bytes)
#define OFF_FHI 0
#define OFF_FLO 34816
#define OFF_CHI 69632                 // c tiles; sim aliases this region after phase A
#define OFF_CLO 87040
#define OFF_SHI 69632                 // sim hi [128][72] bf16 (18432B)
#define OFF_SLO 88064                 // sim lo
#define OFF_F2  106496
#define OFF_C2  107008
#define OFF_SSP 107264                // ssum partials [8][64] f32
#define SMEM_TOTAL 109312

// ---------------- scratch ----------------
__device__ float g_psum[NB * CHUNKS * NK * ND];   // 8 MB
__device__ float g_ssum[NB * CHUNKS * NK];
__device__ float g_sq;
__device__ float g_scale_unused;

// ---------------- helpers ----------------
__device__ __forceinline__ uint32_t smem_u32(const void* p) {
    uint32_t a;
    asm("{ .reg .u64 t; cvta.to.shared.u64 t, %1; cvt.u32.u64 %0, t; }" : "=r"(a) : "l"(p));
    return a;
}
__device__ __forceinline__ unsigned pack_bf2(float a, float b) {
    __nv_bfloat16 ha = __float2bfloat16(a), hb = __float2bfloat16(b);
    unsigned short ua = *reinterpret_cast<unsigned short*>(&ha);
    unsigned short ub = *reinterpret_cast<unsigned short*>(&hb);
    return (unsigned)ua | ((unsigned)ub << 16);
}
__device__ __forceinline__ void split2(float a, float b, uint32_t& hi, uint32_t& lo) {
    __nv_bfloat16 ha = __float2bfloat16(a), hb = __float2bfloat16(b);
    float fa = __bfloat162float(ha), fb = __bfloat162float(hb);
    hi = pack_bf2(a, b);
    lo = pack_bf2(a - fa, b - fb);
}
__device__ __forceinline__ void ldsm_x4(uint32_t* r, uint32_t addr) {
    asm volatile("ldmatrix.sync.aligned.m8n8.x4.shared.b16 {%0,%1,%2,%3}, [%4];"
                 : "=r"(r[0]), "=r"(r[1]), "=r"(r[2]), "=r"(r[3]) : "r"(addr));
}
__device__ __forceinline__ void ldsm_x4_t(uint32_t* r, uint32_t addr) {
    asm volatile("ldmatrix.sync.aligned.m8n8.x4.trans.shared.b16 {%0,%1,%2,%3}, [%4];"
                 : "=r"(r[0]), "=r"(r[1]), "=r"(r[2]), "=r"(r[3]) : "r"(addr));
}
__device__ __forceinline__ void ldsm_x2(uint32_t* r, uint32_t addr) {
    asm volatile("ldmatrix.sync.aligned.m8n8.x2.shared.b16 {%0,%1}, [%2];"
                 : "=r"(r[0]), "=r"(r[1]) : "r"(addr));
}
__device__ __forceinline__ void ldsm_x2_t(uint32_t* r, uint32_t addr) {
    asm volatile("ldmatrix.sync.aligned.m8n8.x2.trans.shared.b16 {%0,%1}, [%2];"
                 : "=r"(r[0]), "=r"(r[1]) : "r"(addr));
}
__device__ __forceinline__ void mma_bf16(float* d, const uint32_t* a, const uint32_t* b) {
    asm volatile("mma.sync.aligned.m16n8k16.row.col.f32.bf16.bf16.f32 "
                 "{%0,%1,%2,%3}, {%4,%5,%6,%7}, {%8,%9}, {%0,%1,%2,%3};"
                 : "+f"(d[0]), "+f"(d[1]), "+f"(d[2]), "+f"(d[3])
                 : "r"(a[0]), "r"(a[1]), "r"(a[2]), "r"(a[3]), "r"(b[0]), "r"(b[1]));
}

// ---------------- stage 1 ----------------
__global__ __launch_bounds__(256, 2)
void nv_stage1(const float* __restrict__ feat, const float* __restrict__ cent) {
    extern __shared__ char smem[];
    const uint32_t sb = smem_u32(smem);
    float* f2  = reinterpret_cast<float*>(smem + OFF_F2);
    float* c2  = reinterpret_cast<float*>(smem + OFF_C2);
    float* ssp = reinterpret_cast<float*>(smem + OFF_SSP);

    const int b     = blockIdx.y;
    const int chunk = blockIdx.x;
    const int tid   = threadIdx.x;
    const int wid   = tid >> 5;
    const int lane  = tid & 31;

    if (blockIdx.x == 0 && blockIdx.y == 0 && tid == 0) g_sq = 0.f;

    const float* cb = cent + (size_t)b * NK * ND;
    const float* fb = feat + (size_t)b * IJ * ND + (size_t)chunk * ROWS * ND;

    // ---- load f: 128 rows; split to bf16 hi/lo; f2 ----
    #pragma unroll
    for (int p = 0; p < 16; p++) {
        int r = wid + 8 * p;
        float4 v = *reinterpret_cast<const float4*>(&fb[r * ND + lane * 4]);
        uint32_t h0, l0, h1, l1;
        split2(v.x, v.y, h0, l0);
        split2(v.z, v.w, h1, l1);
        *reinterpret_cast<uint2*>(smem + OFF_FHI + r * FSTRB + lane * 8) = make_uint2(h0, h1);
        *reinterpret_cast<uint2*>(smem + OFF_FLO + r * FSTRB + lane * 8) = make_uint2(l0, l1);
        float s = v.x * v.x + v.y * v.y + v.z * v.z + v.w * v.w;
        #pragma unroll
        for (int o = 16; o; o >>= 1) s += __shfl_xor_sync(0xffffffffu, s, o);
        if (lane == 0) f2[r] = s;
    }
    // ---- load c: 64 rows ----
    #pragma unroll
    for (int p = 0; p < 8; p++) {
        int k = wid + 8 * p;
        float4 v = *reinterpret_cast<const float4*>(&cb[k * ND + lane * 4]);
        uint32_t h0, l0, h1, l1;
        split2(v.x, v.y, h0, l0);
        split2(v.z, v.w, h1, l1);
        *reinterpret_cast<uint2*>(smem + OFF_CHI + k * FSTRB + lane * 8) = make_uint2(h0, h1);
        *reinterpret_cast<uint2*>(smem + OFF_CLO + k * FSTRB + lane * 8) = make_uint2(l0, l1);
        float s = v.x * v.x + v.y * v.y + v.z * v.z + v.w * v.w;
        #pragma unroll
        for (int o = 16; o; o >>= 1) s += __shfl_xor_sync(0xffffffffu, s, o);
        if (lane == 0) c2[k] = s;
    }
    __syncthreads();

    // ================= phase A: fc = f . c^T  (HMMA bf16x3) =================
    const int r0 = wid * 16;
    float acc[8][4];
    #pragma unroll
    for (int nt = 0; nt < 8; nt++)
        #pragma unroll
        for (int j = 0; j < 4; j++) acc[nt][j] = 0.f;

    {
        // A addresses: row-major m16k16, addr = row*stride + (lane/16)*16B
        uint32_t a_row = (uint32_t)(r0 + ((lane >> 3) & 1) * 8 + (lane & 7));
        uint32_t a_off = a_row * FSTRB + ((uint32_t)(lane >> 4)) * 16;
        uint32_t ah_addr = sb + OFF_FHI + a_off;
        uint32_t al_addr = sb + OFF_FLO + a_off;
        // B addresses: c[n][k] row-major; matrix = (lane&15)/8 selects k-half
        int l = lane & 15;
        uint32_t b_off0 = (uint32_t)(l & 7) * FSTRB + ((uint32_t)(l >> 3)) * 16;

        #pragma unroll
        for (int kk = 0; kk < 8; kk++) {
            uint32_t ko = kk * 32;             // 16 bf16 = 32 bytes
            uint32_t ah[4], al[4];
            ldsm_x4(ah, ah_addr + ko);
            ldsm_x4(al, al_addr + ko);
            #pragma unroll
            for (int nt = 0; nt < 8; nt++) {
                uint32_t bo = sb + OFF_CHI + b_off0 + (uint32_t)(nt * 8) * FSTRB + ko;
                uint32_t bh[2], bl[2];
                ldsm_x2(bh, bo);
                ldsm_x2(bl, bo + (OFF_CLO - OFF_CHI));
                mma_bf16(acc[nt], ah, bh);
                mma_bf16(acc[nt], ah, bl);
                mma_bf16(acc[nt], al, bh);
            }
        }
    }
    __syncthreads();   // all warps done reading c tiles; sim may now alias them

    // ================= softmax (row in a 4-lane group) =================
    {
        const int q  = lane & 3;
        const int ra = r0 + (lane >> 2);
        const int rb = ra + 8;
        const float f2a = f2[ra], f2b = f2[rb];
        float2 c2v[8];
        #pragma unroll
        for (int nt = 0; nt < 8; nt++)
            c2v[nt] = *reinterpret_cast<const float2*>(&c2[nt * 8 + 2 * q]);

        float mxa = -1e30f, mxb = -1e30f;
        #pragma unroll
        for (int nt = 0; nt < 8; nt++) {
            acc[nt][0] = 2.f * acc[nt][0] - f2a - c2v[nt].x;
            acc[nt][1] = 2.f * acc[nt][1] - f2a - c2v[nt].y;
            acc[nt][2] = 2.f * acc[nt][2] - f2b - c2v[nt].x;
            acc[nt][3] = 2.f * acc[nt][3] - f2b - c2v[nt].y;
            mxa = fmaxf(mxa, fmaxf(acc[nt][0], acc[nt][1]));
            mxb = fmaxf(mxb, fmaxf(acc[nt][2], acc[nt][3]));
        }
        #pragma unroll
        for (int o = 1; o <= 2; o <<= 1) {
            mxa = fmaxf(mxa, __shfl_xor_sync(0xffffffffu, mxa, o));
            mxb = fmaxf(mxb, __shfl_xor_sync(0xffffffffu, mxb, o));
        }
        float sa = 0.f, sbm = 0.f;
        #pragma unroll
        for (int nt = 0; nt < 8; nt++) {
            acc[nt][0] = __expf(acc[nt][0] - mxa);
            acc[nt][1] = __expf(acc[nt][1] - mxa);
            acc[nt][2] = __expf(acc[nt][2] - mxb);
            acc[nt][3] = __expf(acc[nt][3] - mxb);
            sa  += acc[nt][0] + acc[nt][1];
            sbm += acc[nt][2] + acc[nt][3];
        }
        #pragma unroll
        for (int o = 1; o <= 2; o <<= 1) {
            sa  += __shfl_xor_sync(0xffffffffu, sa, o);
            sbm += __shfl_xor_sync(0xffffffffu, sbm, o);
        }
        const float inva = 1.f / sa, invb = 1.f / sbm;

        float sk[16];
        #pragma unroll
        for (int nt = 0; nt < 8; nt++) {
            float s0 = acc[nt][0] * inva, s1 = acc[nt][1] * inva;
            float s2 = acc[nt][2] * invb, s3 = acc[nt][3] * invb;
            uint32_t h0, l0, h1, l1;
            split2(s0, s1, h0, l0);
            split2(s2, s3, h1, l1);
            uint32_t co = (uint32_t)(nt * 16 + q * 4);
            *reinterpret_cast<uint32_t*>(smem + OFF_SHI + ra * SSTRB + co) = h0;
            *reinterpret_cast<uint32_t*>(smem + OFF_SLO + ra * SSTRB + co) = l0;
            *reinterpret_cast<uint32_t*>(smem + OFF_SHI + rb * SSTRB + co) = h1;
            *reinterpret_cast<uint32_t*>(smem + OFF_SLO + rb * SSTRB + co) = l1;
            sk[2 * nt]     = s0 + s2;
            sk[2 * nt + 1] = s1 + s3;
        }
        // reduce sim sums over the warp's 16 rows (lanes with same q)
        #pragma unroll
        for (int j = 0; j < 16; j++) {
            sk[j] += __shfl_xor_sync(0xffffffffu, sk[j], 4);
            sk[j] += __shfl_xor_sync(0xffffffffu, sk[j], 8);
            sk[j] += __shfl_xor_sync(0xffffffffu, sk[j], 16);
        }
        if (lane < 4) {
            #pragma unroll
            for (int nt = 0; nt < 8; nt++)
                *reinterpret_cast<float2*>(&ssp[wid * 64 + nt * 8 + 2 * lane]) =
                    make_float2(sk[2 * nt], sk[2 * nt + 1]);
        }
    }
    __syncthreads();

    // ---- finalize ssum ----
    if (tid < 64) {
        float s = 0.f;
        #pragma unroll
        for (int w = 0; w < 8; w++) s += ssp[w * 64 + tid];
        g_ssum[(b * CHUNKS + chunk) * NK + tid] = s;
    }

    // ================= phase B: psum = sim^T . f  (HMMA bf16x3) =================
    {
        const int mt = wid & 3;          // k-tile (16 k)
        const int dh = wid >> 2;         // d-half (64 d)
        float bcc[8][4];
        #pragma unroll
        for (int nt = 0; nt < 8; nt++)
            #pragma unroll
            for (int j = 0; j < 4; j++) bcc[nt][j] = 0.f;

        // A (sim, trans): matrix mi: row_block = mi>>1, col_block = mi&1
        uint32_t mi = (uint32_t)(lane >> 3);
        uint32_t sa_off = ((mi >> 1) * 8 + (uint32_t)(lane & 7)) * SSTRB
                        + ((uint32_t)(mt * 16) + (mi & 1) * 8) * 2;
        // B (f, trans): matrix = (lane&15)/8 selects r-half
        uint32_t fb_row = (((uint32_t)(lane & 15) >> 3) * 8 + (uint32_t)(lane & 7));

        #pragma unroll
        for (int rr = 0; rr < 8; rr++) {
            uint32_t sh[4], sl[4];
            uint32_t sa_addr = sb + OFF_SHI + (uint32_t)(rr * 16) * SSTRB + sa_off;
            ldsm_x4_t(sh, sa_addr);
            ldsm_x4_t(sl, sa_addr + (OFF_SLO - OFF_SHI));
            uint32_t fbase = (uint32_t)(rr * 16) * FSTRB + fb_row * FSTRB;
            #pragma unroll
            for (int nt = 0; nt < 8; nt++) {
                uint32_t n0 = (uint32_t)(dh * 64 + nt * 8);
                uint32_t fh[2], fl[2];
                ldsm_x2_t(fh, sb + OFF_FHI + fbase + n0 * 2);
                ldsm_x2_t(fl, sb + OFF_FLO + fbase + n0 * 2);
                mma_bf16(bcc[nt], sh, fh);
                mma_bf16(bcc[nt], sh, fl);
                mma_bf16(bcc[nt], sl, fh);
            }
        }

        // epilogue: write fragments to g_psum
        const size_t base = ((size_t)(b * CHUNKS + chunk) * NK) * ND;
        const int ka = mt * 16 + (lane >> 2);
        const int kb2 = ka + 8;
        const int dd = dh * 64 + 2 * (lane & 3);
        #pragma unroll
        for (int nt = 0; nt < 8; nt++) {
            *reinterpret_cast<float2*>(&g_psum[base + (size_t)ka * ND + dd + nt * 8]) =
                make_float2(bcc[nt][0], bcc[nt][1]);
            *reinterpret_cast<float2*>(&g_psum[base + (size_t)kb2 * ND + dd + nt * 8]) =
                make_float2(bcc[nt][2], bcc[nt][3]);
        }
    }
}

// ---------------- stage 2: reduce chunks, subtract, atomic sq-sum ---------
__global__ void nv_stage2(const float* __restrict__ cent, float* __restrict__ out) {
    const int g  = blockIdx.x * 128 + threadIdx.x;   // 65536 float4 slots
    const int bk = g >> 5;
    const int b  = bk >> 6;
    const int k  = bk & 63;
    const int d4 = (g & 31) << 2;

    float4 v = make_float4(0.f, 0.f, 0.f, 0.f);
    #pragma unroll
    for (int ch = 0; ch < CHUNKS; ch++) {
        float4 p = *reinterpret_cast<const float4*>(
            &g_psum[(((size_t)(b * CHUNKS + ch) * NK + k) << 7) + d4]);
        v.x += p.x; v.y += p.y; v.z += p.z; v.w += p.w;
    }
    float ss = 0.f;
    #pragma unroll
    for (int ch = 0; ch < CHUNKS; ch++)
        ss += g_ssum[(b * CHUNKS + ch) * NK + k];

    float4 c = *reinterpret_cast<const float4*>(&cent[(((size_t)b * NK + k) << 7) + d4]);
    float4 o;
    o.x = v.x - ss * c.x; o.y = v.y - ss * c.y;
    o.z = v.z - ss * c.z; o.w = v.w - ss * c.w;
    *reinterpret_cast<float4*>(&out[(((size_t)b * NK + k) << 7) + d4]) = o;

    float sq = o.x * o.x + o.y * o.y + o.z * o.z + o.w * o.w;
    #pragma unroll
    for (int off = 16; off; off >>= 1) sq += __shfl_xor_sync(0xffffffffu, sq, off);
    __shared__ float red[4];
    if ((threadIdx.x & 31) == 0) red[threadIdx.x >> 5] = sq;
    __syncthreads();
    if (threadIdx.x == 0)
        atomicAdd(&g_sq, red[0] + red[1] + red[2] + red[3]);
}

// ---------------- stage 3: apply global scale ------------------------------
__global__ void nv_stage4(float* __restrict__ out) {
    const int i = blockIdx.x * blockDim.x + threadIdx.x;   // 65536 float4
    const float sc = rsqrtf(fmaxf(g_sq, 1e-12f));
    float4* o4 = reinterpret_cast<float4*>(out);
    float4 v = o4[i];
    v.x *= sc; v.y *= sc; v.z *= sc; v.w *= sc;
    o4[i] = v;
}

// ---------------- launch ----------------------------------------------------
extern "C" void kernel_launch(void* const* d_in, const int* in_sizes, int n_in,
                              void* d_out, int out_size) {
    const float* feat = (const float*)d_in[0];   // (32,32,32,128) fp32
    const float* cent = (const float*)d_in[1];   // (32,64,128)    fp32
    float* out = (float*)d_out;                  // (32, 8192)     fp32

    cudaFuncSetAttribute(nv_stage1, cudaFuncAttributeMaxDynamicSharedMemorySize, SMEM_TOTAL);

    nv_stage1<<<dim3(CHUNKS, NB), 256, SMEM_TOTAL>>>(feat, cent);
    nv_stage2<<<512, 128>>>(cent, out);
    nv_stage4<<<256, 256>>>(out);
}